// round 16
// baseline (speedup 1.0000x reference)
#include <cuda_runtime.h>
#include <cuda_bf16.h>
#include <cstdint>

// ---------------------------------------------------------------------------
// Problem constants
// ---------------------------------------------------------------------------
#define B_SZ     8
#define N_PTS    131072
#define IN_C     64
#define OUT_C    64
#define STYLE_D  256
#define EPS_V    1e-8f

#define TILE_M   128          // points per tile
#define THREADS  256          // 8 warps: 4 m-groups x 2 n-groups
#define CTAS_X   64           // CTAs per batch; each does 1024/64 = 16 tiles
#define TILES_PER_CTA (N_PTS / TILE_M / CTAS_X)   // 16

// Per-batch modulated weights, bf16-split, linear [o][k] (64x64 each)
__device__ __align__(16) __nv_bfloat16 g_Whi[B_SZ][OUT_C * IN_C];
__device__ __align__(16) __nv_bfloat16 g_Wlo[B_SZ][OUT_C * IN_C];

// ---------------------------------------------------------------------------
// Kernel A: build weights, split to bf16 hi/lo. Negligible cost.
// ---------------------------------------------------------------------------
__global__ void modw_kernel(const float* __restrict__ style,
                            const float* __restrict__ weight,
                            const float* __restrict__ mod_weight,
                            const float* __restrict__ mod_bias) {
    const int b = blockIdx.x;
    const int t = threadIdx.x;             // 0..63 = output channel o
    __shared__ float s_sh[IN_C];

    const float mod_scale = 0.0625f;       // 1/sqrt(256)
    const float* st = style + b * STYLE_D;
    const float* mw = mod_weight + t * STYLE_D;
    float acc = 0.f;
    #pragma unroll 8
    for (int d = 0; d < STYLE_D; d += 4) {
        float4 a = *(const float4*)(st + d);
        float4 m = *(const float4*)(mw + d);
        acc += a.x * m.x + a.y * m.y + a.z * m.z + a.w * m.w;
    }
    s_sh[t] = acc * mod_scale + mod_bias[t] + 1.0f;
    __syncthreads();

    const float scale = 0.125f;            // 1/sqrt(64)
    const float* wr = weight + t * IN_C;
    float ss = 0.f;
    #pragma unroll 16
    for (int i = 0; i < IN_C; i++) {
        float v = scale * wr[i] * s_sh[i];
        ss += v * v;
    }
    float demod = rsqrtf(ss + EPS_V);
    #pragma unroll 16
    for (int i = 0; i < IN_C; i++) {
        float v = scale * wr[i] * s_sh[i] * demod;
        __nv_bfloat16 vh = __float2bfloat16(v);
        __nv_bfloat16 vl = __float2bfloat16(v - __bfloat162float(vh));
        g_Whi[b][t * IN_C + i] = vh;
        g_Wlo[b][t * IN_C + i] = vl;
    }
}

// ---------------------------------------------------------------------------
// Primitives (plain sm_80+ features; NO tcgen05 — harness compiles a
// compute_103 (non-'a') PTX stage where tcgen05 is rejected).
// ---------------------------------------------------------------------------
__device__ __forceinline__ uint32_t smem_u32(const void* p) {
    uint32_t a;
    asm("{ .reg .u64 t; cvta.to.shared.u64 t, %1; cvt.u32.u64 %0, t; }"
        : "=r"(a) : "l"(p));
    return a;
}

#define LDSM4(r, a) \
    asm volatile("ldmatrix.sync.aligned.m8n8.x4.shared.b16 {%0,%1,%2,%3}, [%4];" \
        : "=r"((r)[0]), "=r"((r)[1]), "=r"((r)[2]), "=r"((r)[3]) : "r"(a))

#define MMA16816(c, a, b0, b1) \
    asm volatile("mma.sync.aligned.m16n8k16.row.col.f32.bf16.bf16.f32 " \
        "{%0,%1,%2,%3}, {%4,%5,%6,%7}, {%8,%9}, {%0,%1,%2,%3};" \
        : "+f"((c)[0]), "+f"((c)[1]), "+f"((c)[2]), "+f"((c)[3]) \
        : "r"((a)[0]), "r"((a)[1]), "r"((a)[2]), "r"((a)[3]), \
          "r"(b0), "r"(b1))

#define CP_ASYNC16(sdst, gsrc) \
    asm volatile("cp.async.ca.shared.global [%0], [%1], 16;" \
        :: "r"(sdst), "l"(gsrc) : "memory")
#define CP_COMMIT()  asm volatile("cp.async.commit_group;" ::: "memory")
#define CP_WAIT0()   asm volatile("cp.async.wait_group 0;"  ::: "memory")

#define PREFETCH_L2(p) \
    asm volatile("prefetch.global.L2 [%0];" :: "l"(p))

// ---------------------------------------------------------------------------
// SMEM layout. Pitch 144B makes every ldmatrix phase conflict-free
// (row stride mod 128 = 16 walks all eight 16B bank groups).
// ---------------------------------------------------------------------------
#define W_PITCH   144
#define A_PITCH   144
#define SM_W_HI   0
#define SM_W_LO   (OUT_C * W_PITCH)                 //  9216
#define SM_A_HI   (SM_W_LO + OUT_C * W_PITCH)      // 18432
#define SM_A_LO   (SM_A_HI + TILE_M * A_PITCH)     // 36864
#define SM_TOTAL  (SM_A_LO + TILE_M * A_PITCH)     // 55296
// Output overlay aliases the A region after compute (128*272 = 34816B)
#define OUT_OVL   SM_A_HI
#define OUT_PITCH 68                                // floats per row (272B)

// ---------------------------------------------------------------------------
// Kernel B: bf16x3 GEMM via mma.sync (R13 body), persistent over 16 tiles.
// W staged ONCE per CTA; next tile's X prefetched to L2 during current tile
// so the staging LDGs hit L2 (~240cyc) instead of DRAM (~577cyc).
// ---------------------------------------------------------------------------
__global__ __launch_bounds__(THREADS, 3)
void modconv_mma(const float* __restrict__ x,
                 const float* __restrict__ bias,
                 float* __restrict__ out) {
    extern __shared__ __align__(16) char smem[];
    const uint32_t sb = smem_u32(smem);
    const int tid = threadIdx.x;
    const int wid = tid >> 5;
    const int lid = tid & 31;
    const int b   = blockIdx.y;

    // ---- stage W once via cp.async ----
    {
        const char* whi = (const char*)g_Whi[b];
        const char* wlo = (const char*)g_Wlo[b];
        #pragma unroll
        for (int it = 0; it < 2; it++) {
            int idx = tid + it * THREADS;            // 0..511
            int o = idx >> 3, c = idx & 7;           // row, 16B chunk
            CP_ASYNC16(sb + SM_W_HI + o * W_PITCH + c * 16, whi + idx * 16);
            CP_ASYNC16(sb + SM_W_LO + o * W_PITCH + c * 16, wlo + idx * 16);
        }
        CP_COMMIT();
    }

    // ---- warp tiling / lane mapping (R13) ----
    const int mBase = (wid & 3) * 32;                // point rows
    const int oBase = (wid >> 2) * 32;               // output cols
    const int mi    = lid >> 3;
    const int l7    = lid & 7;
    const int a_row = (mi & 1) * 8 + l7;
    const int a_kh  = mi >> 1;
    const int w_row = (mi >> 1) * 8 + l7;
    const int w_kh  = mi & 1;

    // prefetch first tile while W lands
    {
        const char* xg = (const char*)(x + ((long)b * N_PTS +
                          (long)blockIdx.x * TILE_M) * IN_C);
        PREFETCH_L2(xg + tid * 128);                 // 256 x 128B = 32KB
    }
    CP_WAIT0();
    __syncthreads();

    for (int tIdx = 0; tIdx < TILES_PER_CTA; tIdx++) {
        const long tile = (long)blockIdx.x + (long)tIdx * CTAS_X;
        const long gbase = ((long)b * N_PTS + tile * TILE_M) * IN_C;

        // ---- prefetch NEXT tile to L2 (1 line per thread) ----
        if (tIdx + 1 < TILES_PER_CTA) {
            const char* xn = (const char*)(x + (gbase +
                              (long)CTAS_X * TILE_M * IN_C));
            PREFETCH_L2(xn + tid * 128);
        }

        // ---- stage X: coalesced fp32 load (L2-hit), split hi/lo bf16 ----
        {
            const float4* xin4 = (const float4*)(x + gbase);
            #pragma unroll
            for (int it = 0; it < 8; it++) {
                int idx = tid + it * THREADS;        // 0..2047
                int p = idx >> 4, c = idx & 15;      // point, k-chunk of 4
                float4 v = xin4[idx];
                __nv_bfloat162 h0 = __floats2bfloat162_rn(v.x, v.y);
                __nv_bfloat162 h1 = __floats2bfloat162_rn(v.z, v.w);
                float lx = v.x - __bfloat162float(__low2bfloat16(h0));
                float ly = v.y - __bfloat162float(__high2bfloat16(h0));
                float lz = v.z - __bfloat162float(__low2bfloat16(h1));
                float lw = v.w - __bfloat162float(__high2bfloat16(h1));
                __nv_bfloat162 l0 = __floats2bfloat162_rn(lx, ly);
                __nv_bfloat162 l1 = __floats2bfloat162_rn(lz, lw);
                uint2 uh, ul;
                uh.x = *(uint32_t*)&h0;  uh.y = *(uint32_t*)&h1;
                ul.x = *(uint32_t*)&l0;  ul.y = *(uint32_t*)&l1;
                *(uint2*)(smem + SM_A_HI + p * A_PITCH + c * 8) = uh;
                *(uint2*)(smem + SM_A_LO + p * A_PITCH + c * 8) = ul;
            }
        }
        __syncthreads();

        float C[2][4][4];
        #pragma unroll
        for (int i = 0; i < 2; i++)
            #pragma unroll
            for (int j = 0; j < 4; j++)
                #pragma unroll
                for (int q = 0; q < 4; q++) C[i][j][q] = 0.f;

        // ---- main loop: 4 k-steps, 24 HMMA each ----
        #pragma unroll
        for (int ks = 0; ks < 4; ks++) {
            uint32_t AH[2][4], AL[2][4], WH[2][4], WL[2][4];
            #pragma unroll
            for (int mf = 0; mf < 2; mf++) {
                uint32_t off = (mBase + mf * 16 + a_row) * A_PITCH
                             + ks * 32 + a_kh * 16;
                LDSM4(AH[mf], sb + SM_A_HI + off);
                LDSM4(AL[mf], sb + SM_A_LO + off);
            }
            #pragma unroll
            for (int nb = 0; nb < 2; nb++) {
                uint32_t woff = (oBase + nb * 16 + w_row) * W_PITCH
                              + ks * 32 + w_kh * 16;
                LDSM4(WH[nb], sb + SM_W_HI + woff);
                LDSM4(WL[nb], sb + SM_W_LO + woff);
            }
            #pragma unroll
            for (int mf = 0; mf < 2; mf++)
                #pragma unroll
                for (int nf = 0; nf < 4; nf++) {
                    const int nb = nf >> 1, sel = (nf & 1) * 2;
                    float* c = C[mf][nf];
                    MMA16816(c, AH[mf], WH[nb][sel], WH[nb][sel + 1]);
                    MMA16816(c, AL[mf], WH[nb][sel], WH[nb][sel + 1]);
                    MMA16816(c, AH[mf], WL[nb][sel], WL[nb][sel + 1]);
                }
        }

        // ---- epilogue: bias add, padded overlay (aliases A), coalesced STG
        __syncthreads();                   // all warps done reading A region
        {
            float* ovl = (float*)(smem + OUT_OVL);
            const int g = lid >> 2, t2 = (lid & 3) * 2;
            #pragma unroll
            for (int mf = 0; mf < 2; mf++)
                #pragma unroll
                for (int nf = 0; nf < 4; nf++) {
                    const int col = oBase + nf * 8 + t2;
                    const float b0 = __ldg(bias + col);
                    const float b1 = __ldg(bias + col + 1);
                    const int r0 = mBase + mf * 16 + g;
                    float* c = C[mf][nf];
                    *(float2*)(ovl + r0 * OUT_PITCH + col) =
                        make_float2(c[0] + b0, c[1] + b1);
                    *(float2*)(ovl + (r0 + 8) * OUT_PITCH + col) =
                        make_float2(c[2] + b0, c[3] + b1);
                }
        }
        __syncthreads();
        {
            const float* ovl = (const float*)(smem + OUT_OVL);
            float4* out4 = (float4*)(out + gbase);
            #pragma unroll
            for (int it = 0; it < 8; it++) {
                int idx = tid + it * THREADS;        // 0..2047
                int p = idx >> 4, c = idx & 15;
                out4[idx] = *(const float4*)(ovl + p * OUT_PITCH + c * 4);
            }
        }
        __syncthreads();                   // overlay consumed before next stage
    }
}

// ---------------------------------------------------------------------------
// Launch
// inputs: 0=x, 1=style, 2=weight, 3=bias, 4=mod_weight, 5=mod_bias
// ---------------------------------------------------------------------------
extern "C" void kernel_launch(void* const* d_in, const int* in_sizes, int n_in,
                              void* d_out, int out_size) {
    const float* x          = (const float*)d_in[0];
    const float* style      = (const float*)d_in[1];
    const float* weight     = (const float*)d_in[2];
    const float* bias       = (const float*)d_in[3];
    const float* mod_weight = (const float*)d_in[4];
    const float* mod_bias   = (const float*)d_in[5];
    float* out = (float*)d_out;

    cudaFuncSetAttribute(modconv_mma,
                         cudaFuncAttributeMaxDynamicSharedMemorySize, SM_TOTAL);

    modw_kernel<<<B_SZ, 64>>>(style, weight, mod_weight, mod_bias);

    dim3 grid(CTAS_X, B_SZ);
    modconv_mma<<<grid, THREADS, SM_TOTAL>>>(x, bias, out);
}

// round 17
// speedup vs baseline: 1.0872x; 1.0872x over previous
#include <cuda_runtime.h>
#include <cuda_bf16.h>
#include <cstdint>

// ---------------------------------------------------------------------------
// Problem constants
// ---------------------------------------------------------------------------
#define B_SZ     8
#define N_PTS    131072
#define IN_C     64
#define OUT_C    64
#define STYLE_D  256
#define EPS_V    1e-8f

#define TILE_M   128          // points per CTA
#define THREADS  256          // 8 warps: 4 m-groups x 2 n-groups

// Per-batch modulated weights, bf16-split, linear [o][k] (64x64 each)
__device__ __align__(16) __nv_bfloat16 g_Whi[B_SZ][OUT_C * IN_C];
__device__ __align__(16) __nv_bfloat16 g_Wlo[B_SZ][OUT_C * IN_C];

// ---------------------------------------------------------------------------
// Kernel A: build weights, split to bf16 hi/lo. Negligible cost.
// ---------------------------------------------------------------------------
__global__ void modw_kernel(const float* __restrict__ style,
                            const float* __restrict__ weight,
                            const float* __restrict__ mod_weight,
                            const float* __restrict__ mod_bias) {
    const int b = blockIdx.x;
    const int t = threadIdx.x;             // 0..63 = output channel o
    __shared__ float s_sh[IN_C];

    const float mod_scale = 0.0625f;       // 1/sqrt(256)
    const float* st = style + b * STYLE_D;
    const float* mw = mod_weight + t * STYLE_D;
    float acc = 0.f;
    #pragma unroll 8
    for (int d = 0; d < STYLE_D; d += 4) {
        float4 a = *(const float4*)(st + d);
        float4 m = *(const float4*)(mw + d);
        acc += a.x * m.x + a.y * m.y + a.z * m.z + a.w * m.w;
    }
    s_sh[t] = acc * mod_scale + mod_bias[t] + 1.0f;
    __syncthreads();

    const float scale = 0.125f;            // 1/sqrt(64)
    const float* wr = weight + t * IN_C;
    float ss = 0.f;
    #pragma unroll 16
    for (int i = 0; i < IN_C; i++) {
        float v = scale * wr[i] * s_sh[i];
        ss += v * v;
    }
    float demod = rsqrtf(ss + EPS_V);
    #pragma unroll 16
    for (int i = 0; i < IN_C; i++) {
        float v = scale * wr[i] * s_sh[i] * demod;
        __nv_bfloat16 vh = __float2bfloat16(v);
        __nv_bfloat16 vl = __float2bfloat16(v - __bfloat162float(vh));
        g_Whi[b][t * IN_C + i] = vh;
        g_Wlo[b][t * IN_C + i] = vl;
    }
}

// ---------------------------------------------------------------------------
// Primitives (plain sm_80+ features; NO tcgen05 — harness compiles a
// compute_103 (non-'a') PTX stage where tcgen05 is rejected).
// ---------------------------------------------------------------------------
__device__ __forceinline__ uint32_t smem_u32(const void* p) {
    uint32_t a;
    asm("{ .reg .u64 t; cvta.to.shared.u64 t, %1; cvt.u32.u64 %0, t; }"
        : "=r"(a) : "l"(p));
    return a;
}

#define LDSM4(r, a) \
    asm volatile("ldmatrix.sync.aligned.m8n8.x4.shared.b16 {%0,%1,%2,%3}, [%4];" \
        : "=r"((r)[0]), "=r"((r)[1]), "=r"((r)[2]), "=r"((r)[3]) : "r"(a))

#define MMA16816(c, a, b0, b1) \
    asm volatile("mma.sync.aligned.m16n8k16.row.col.f32.bf16.bf16.f32 " \
        "{%0,%1,%2,%3}, {%4,%5,%6,%7}, {%8,%9}, {%0,%1,%2,%3};" \
        : "+f"((c)[0]), "+f"((c)[1]), "+f"((c)[2]), "+f"((c)[3]) \
        : "r"((a)[0]), "r"((a)[1]), "r"((a)[2]), "r"((a)[3]), \
          "r"(b0), "r"(b1))

#define CP_ASYNC16(sdst, gsrc) \
    asm volatile("cp.async.ca.shared.global [%0], [%1], 16;" \
        :: "r"(sdst), "l"(gsrc) : "memory")
#define CP_COMMIT()  asm volatile("cp.async.commit_group;" ::: "memory")
#define CP_WAIT0()   asm volatile("cp.async.wait_group 0;"  ::: "memory")

// ---------------------------------------------------------------------------
// SMEM layout. Pitch 144B (= 128+16) makes every ldmatrix phase conflict-free
// (row stride mod 128 = 16 walks all eight 16B bank groups).
// ---------------------------------------------------------------------------
#define W_PITCH   144
#define A_PITCH   144
#define SM_W_HI   0
#define SM_W_LO   (OUT_C * W_PITCH)                 //  9216
#define SM_A_HI   (SM_W_LO + OUT_C * W_PITCH)      // 18432
#define SM_A_LO   (SM_A_HI + TILE_M * A_PITCH)     // 36864
#define SM_TOTAL  (SM_A_LO + TILE_M * A_PITCH)     // 55296
// Output overlay aliases the A region after compute (needs 128*272 = 34816B)
#define OUT_OVL   SM_A_HI
#define OUT_PITCH 68                                // floats per row (272B)

// ---------------------------------------------------------------------------
// Kernel B: bf16x3 GEMM via mma.sync — R13 body, but the k-loop consumes W
// fragments nb-sequentially to shrink the live register set, and
// launch_bounds(256,4) targets 4 CTAs/SM (smem: 4 x 55.3KB = 221KB <= 228KB).
// ---------------------------------------------------------------------------
__global__ __launch_bounds__(THREADS, 4)
void modconv_mma(const float* __restrict__ x,
                 const float* __restrict__ bias,
                 float* __restrict__ out) {
    extern __shared__ __align__(16) char smem[];
    const uint32_t sb = smem_u32(smem);
    const int tid = threadIdx.x;
    const int wid = tid >> 5;
    const int lid = tid & 31;
    const int b   = blockIdx.y;
    const long gbase = ((long)b * N_PTS + (long)blockIdx.x * TILE_M) * IN_C;

    // ---- stage W tiles via cp.async (no register round-trip) ----
    {
        const char* whi = (const char*)g_Whi[b];
        const char* wlo = (const char*)g_Wlo[b];
        #pragma unroll
        for (int it = 0; it < 2; it++) {
            int idx = tid + it * THREADS;            // 0..511
            int o = idx >> 3, c = idx & 7;           // row, 16B chunk
            CP_ASYNC16(sb + SM_W_HI + o * W_PITCH + c * 16, whi + idx * 16);
            CP_ASYNC16(sb + SM_W_LO + o * W_PITCH + c * 16, wlo + idx * 16);
        }
        CP_COMMIT();
    }
    // ---- stage X: coalesced fp32 load, split hi/lo bf16 ----
    {
        const float4* xin4 = (const float4*)(x + gbase);
        #pragma unroll
        for (int it = 0; it < 8; it++) {
            int idx = tid + it * THREADS;            // 0..2047
            int p = idx >> 4, c = idx & 15;          // point, k-chunk of 4
            float4 v = xin4[idx];
            __nv_bfloat162 h0 = __floats2bfloat162_rn(v.x, v.y);
            __nv_bfloat162 h1 = __floats2bfloat162_rn(v.z, v.w);
            float lx = v.x - __bfloat162float(__low2bfloat16(h0));
            float ly = v.y - __bfloat162float(__high2bfloat16(h0));
            float lz = v.z - __bfloat162float(__low2bfloat16(h1));
            float lw = v.w - __bfloat162float(__high2bfloat16(h1));
            __nv_bfloat162 l0 = __floats2bfloat162_rn(lx, ly);
            __nv_bfloat162 l1 = __floats2bfloat162_rn(lz, lw);
            uint2 uh, ul;
            uh.x = *(uint32_t*)&h0;  uh.y = *(uint32_t*)&h1;
            ul.x = *(uint32_t*)&l0;  ul.y = *(uint32_t*)&l1;
            *(uint2*)(smem + SM_A_HI + p * A_PITCH + c * 8) = uh;
            *(uint2*)(smem + SM_A_LO + p * A_PITCH + c * 8) = ul;
        }
    }
    CP_WAIT0();
    __syncthreads();

    // ---- warp tiling ----
    const int mBase = (wid & 3) * 32;                // point rows
    const int oBase = (wid >> 2) * 32;               // output cols
    const int mi    = lid >> 3;
    const int l7    = lid & 7;
    const int a_row = (mi & 1) * 8 + l7;             // A ldmatrix lane rows
    const int a_kh  = mi >> 1;
    const int w_row = (mi >> 1) * 8 + l7;            // W ldmatrix lane rows
    const int w_kh  = mi & 1;

    float C[2][4][4];
    #pragma unroll
    for (int i = 0; i < 2; i++)
        #pragma unroll
        for (int j = 0; j < 4; j++)
            #pragma unroll
            for (int q = 0; q < 4; q++) C[i][j][q] = 0.f;

    // ---- main loop: 4 k-steps; W consumed nb-sequentially (low live set) ----
    #pragma unroll
    for (int ks = 0; ks < 4; ks++) {
        uint32_t AH[2][4], AL[2][4];
        #pragma unroll
        for (int mf = 0; mf < 2; mf++) {
            uint32_t off = (mBase + mf * 16 + a_row) * A_PITCH + ks * 32 + a_kh * 16;
            LDSM4(AH[mf], sb + SM_A_HI + off);
            LDSM4(AL[mf], sb + SM_A_LO + off);
        }
        #pragma unroll
        for (int nb = 0; nb < 2; nb++) {
            uint32_t WH[4], WL[4];
            uint32_t woff = (oBase + nb * 16 + w_row) * W_PITCH + ks * 32 + w_kh * 16;
            LDSM4(WH, sb + SM_W_HI + woff);
            LDSM4(WL, sb + SM_W_LO + woff);
            #pragma unroll
            for (int mf = 0; mf < 2; mf++)
                #pragma unroll
                for (int half = 0; half < 2; half++) {
                    const int sel = half * 2;
                    float* c = C[mf][nb * 2 + half];
                    MMA16816(c, AH[mf], WH[sel], WH[sel + 1]);
                    MMA16816(c, AL[mf], WH[sel], WH[sel + 1]);
                    MMA16816(c, AH[mf], WL[sel], WL[sel + 1]);
                }
        }
    }

    // ---- epilogue: bias add, padded-SMEM overlay (aliases A), coalesced STG
    __syncthreads();                       // all warps done reading A region
    {
        float* ovl = (float*)(smem + OUT_OVL);
        const int g = lid >> 2, t2 = (lid & 3) * 2;
        #pragma unroll
        for (int mf = 0; mf < 2; mf++)
            #pragma unroll
            for (int nf = 0; nf < 4; nf++) {
                const int col = oBase + nf * 8 + t2;
                const float b0 = __ldg(bias + col);
                const float b1 = __ldg(bias + col + 1);
                const int r0 = mBase + mf * 16 + g;
                float* c = C[mf][nf];
                *(float2*)(ovl + r0 * OUT_PITCH + col) =
                    make_float2(c[0] + b0, c[1] + b1);
                *(float2*)(ovl + (r0 + 8) * OUT_PITCH + col) =
                    make_float2(c[2] + b0, c[3] + b1);
            }
    }
    __syncthreads();
    {
        const float* ovl = (const float*)(smem + OUT_OVL);
        float4* out4 = (float4*)(out + gbase);
        #pragma unroll
        for (int it = 0; it < 8; it++) {
            int idx = tid + it * THREADS;            // 0..2047
            int p = idx >> 4, c = idx & 15;
            out4[idx] = *(const float4*)(ovl + p * OUT_PITCH + c * 4);
        }
    }
}

// ---------------------------------------------------------------------------
// Launch
// inputs: 0=x, 1=style, 2=weight, 3=bias, 4=mod_weight, 5=mod_bias
// ---------------------------------------------------------------------------
extern "C" void kernel_launch(void* const* d_in, const int* in_sizes, int n_in,
                              void* d_out, int out_size) {
    const float* x          = (const float*)d_in[0];
    const float* style      = (const float*)d_in[1];
    const float* weight     = (const float*)d_in[2];
    const float* bias       = (const float*)d_in[3];
    const float* mod_weight = (const float*)d_in[4];
    const float* mod_bias   = (const float*)d_in[5];
    float* out = (float*)d_out;

    cudaFuncSetAttribute(modconv_mma,
                         cudaFuncAttributeMaxDynamicSharedMemorySize, SM_TOTAL);

    modw_kernel<<<B_SZ, 64>>>(style, weight, mod_weight, mod_bias);

    dim3 grid(N_PTS / TILE_M, B_SZ);
    modconv_mma<<<grid, THREADS, SM_TOTAL>>>(x, bias, out);
}